// round 10
// baseline (speedup 1.0000x reference)
#include <cuda_runtime.h>
#include <cuda_fp16.h>
#include <cuda_bf16.h>
#include <math.h>

// Problem constants (match reference_code)
#define HH 256
#define WW 336
#define HWPIX (HH * WW)            // 86016
#define BB 8
#define NEV 262144
#define FLOW_SCALING 336.0f
#define REG_WEIGHT 0.001f

// ---------------------------------------------------------------------------
// Accumulator: 16B "quad" entries, 4 parity-shifted copies.
// Quad (16B) = 4 cells f16x2 {iwe, iwe_ts}:
//   lane0=(y0,x0) lane1=(y0,x0+1) lane2=(y0+1,x0) lane3=(y0+1,x0+1)
// Copy (cy,cx): quad(j,k) covers rows 2j-cy..2j-cy+1, cols 2k-cx..2k-cx+1.
// Bilinear block (ty..ty+1, lx..lx+1) -> ONE aligned quad in copy (ty&1, lx&1).
// ---------------------------------------------------------------------------
#define NPLANES 32                 // b(8) x tref(2) x p(2)
#define RP 130
#define XP 170
#define COPY_ENT ((size_t)RP * XP)            // 22100 quads
#define PLANE_ENT (4 * COPY_ENT)              // 88400 quads
#define NQUAD ((size_t)NPLANES * PLANE_ENT)   // ~45MB

#define NULL_WORDS (NQUAD * 2)
__device__ __align__(16) unsigned long long g_acc[NULL_WORDS + 2];

#define G_LOSS_PTR (reinterpret_cast<double*>(&g_acc[NULL_WORDS]))
#define G_CTR_PTR  (reinterpret_cast<unsigned int*>(&g_acc[NULL_WORDS + 1]))

__device__ __forceinline__ void red_quad(void* entry,
                                         __half2 a, __half2 b, __half2 c, __half2 d) {
    unsigned int ua = *reinterpret_cast<unsigned int*>(&a);
    unsigned int ub = *reinterpret_cast<unsigned int*>(&b);
    unsigned int uc = *reinterpret_cast<unsigned int*>(&c);
    unsigned int ud = *reinterpret_cast<unsigned int*>(&d);
    asm volatile("red.global.add.noftz.v4.f16x2 [%0], {%1, %2, %3, %4};"
                 :: "l"(entry), "r"(ua), "r"(ub), "r"(uc), "r"(ud) : "memory");
}

// ---------------------------------------------------------------------------
// Scatter: grid (NEV/256, B). One thread per event, 2 REDs per event.
// ---------------------------------------------------------------------------
__global__ void __launch_bounds__(256) scatter_kernel(
    const float* __restrict__ flow,       // [B,2,H,W]
    const float* __restrict__ event_list) // [B,N,4] = {t, y, x, pol(+-1)}
{
    const int i = blockIdx.x * 256 + threadIdx.x;   // event index within batch
    const int b = blockIdx.y;

    const float4 e = reinterpret_cast<const float4*>(event_list)[(size_t)b * NEV + i];
    const float ts = e.x;
    const float yy = e.y;
    const float xx = e.z;
    const int   p  = (e.w > 0.0f) ? 0 : 1;   // pol_mask: col0=(pol==1), col1=(pol==0)

    const int pix = (int)yy * WW + (int)xx;
    const float* fb = flow + (size_t)b * 2 * HWPIX;
    const float dxf = fb[pix] * FLOW_SCALING;           // x-flow * scale
    const float dyf = fb[HWPIX + pix] * FLOW_SCALING;   // y-flow * scale

    // tref=0: w = pos - ts*flow ; tref=1: w = pos + (1-ts)*flow = w0 + flow
    const float wy_t[2] = { fmaf(-ts, dyf, yy), fmaf(-ts, dyf, yy) + dyf };
    const float wx_t[2] = { fmaf(-ts, dxf, xx), fmaf(-ts, dxf, xx) + dxf };

#pragma unroll
    for (int tref = 0; tref < 2; ++tref) {
        const float wy = wy_t[tref];
        const float wx = wx_t[tref];
        const float tg = tref ? ts : (1.0f - ts);

        const float tyf = floorf(wy);
        const float lxf = floorf(wx);
        const int ty = (int)tyf;
        const int lx = (int)lxf;
        const float fry = wy - tyf;
        const float frx = wx - lxf;

        const float wy0 = ((unsigned)ty       < HH) ? (1.0f - fry) : 0.0f;
        const float wy1 = ((unsigned)(ty + 1) < HH) ? fry          : 0.0f;
        const float wxl = ((unsigned)lx       < WW) ? (1.0f - frx) : 0.0f;
        const float wxr = ((unsigned)(lx + 1) < WW) ? frx          : 0.0f;

        if ((wy0 + wy1) * (wxl + wxr) == 0.0f) continue;

        const int tyc = min(max(ty, -1), HH - 1);
        const int lxc = min(max(lx, -1), WW - 1);

        const int cy = tyc & 1;
        const int cx = lxc & 1;
        const int j  = (tyc + cy) >> 1;
        const int k  = (lxc + cx) >> 1;
        const int plane = ((b * 2 + tref) * 2 + p);

        const size_t entry = (size_t)plane * PLANE_ENT
                           + (size_t)(cy * 2 + cx) * COPY_ENT
                           + (size_t)j * XP + k;

        const float w00 = wy0 * wxl, w01 = wy0 * wxr;
        const float w10 = wy1 * wxl, w11 = wy1 * wxr;

        red_quad(reinterpret_cast<char*>(g_acc) + entry * 16,
                 __floats2half2_rn(w00, w00 * tg),
                 __floats2half2_rn(w01, w01 * tg),
                 __floats2half2_rn(w10, w10 * tg),
                 __floats2half2_rn(w11, w11 * tg));
    }
}

// ---------------------------------------------------------------------------
// Block reduction helper (f32 partials -> double atomic)
// ---------------------------------------------------------------------------
__device__ __forceinline__ void block_reduce_add(float v) {
    __shared__ float sdata[32];
    const int lane = threadIdx.x & 31;
    const int warp = threadIdx.x >> 5;
#pragma unroll
    for (int off = 16; off > 0; off >>= 1)
        v += __shfl_down_sync(0xffffffffu, v, off);
    if (lane == 0) sdata[warp] = v;
    __syncthreads();
    if (warp == 0) {
        const int nwarps = (blockDim.x + 31) >> 5;
        float s = (lane < nwarps) ? sdata[lane] : 0.0f;
#pragma unroll
        for (int off = 16; off > 0; off >>= 1)
            s += __shfl_down_sync(0xffffffffu, s, off);
        if (lane == 0) atomicAdd(G_LOSS_PTR, (double)s);
    }
}

// ---------------------------------------------------------------------------
// Fused reduce, 3D grid: (2, 32, 33).
//   z in [0,32): accumulator planes; each block covers 8 rows x half the width.
//   z == 32:     flow smoothness (grid-stride).
// Last finishing block writes the output scalar.
// ---------------------------------------------------------------------------
#define RBX 192          // threads per block (168 active on cell work)
#define RXW 168          // cells per block in x

__global__ void __launch_bounds__(RBX) fused_reduce_kernel(
    const float* __restrict__ flow, float* __restrict__ out)
{
    float sum = 0.0f;

    if (blockIdx.z < NPLANES) {
        const int plane = blockIdx.z;
        const int x = blockIdx.x * RXW + threadIdx.x;

        if (threadIdx.x < RXW) {
            const unsigned int* pu = reinterpret_cast<const unsigned int*>(g_acc)
                                   + (size_t)plane * PLANE_ENT * 4;
            // x-dependent (lane) address parts for cx=0 / cx=1
            const unsigned xp0 = ((unsigned)(x)     >> 1 << 2) + (x & 1);
            const unsigned xp1 = ((unsigned)(x + 1) >> 1 << 2) + ((x + 1) & 1);

#pragma unroll
            for (int r = 0; r < 8; ++r) {
                const int y = blockIdx.y * 8 + r;
                // block-uniform row bases per copy (cy,cx)
                const unsigned rb00 = ((0u * COPY_ENT + ((unsigned)y       >> 1) * XP) << 2) + (((y)     & 1) << 1);
                const unsigned rb01 = ((1u * COPY_ENT + ((unsigned)y       >> 1) * XP) << 2) + (((y)     & 1) << 1);
                const unsigned rb10 = ((2u * COPY_ENT + ((unsigned)(y + 1) >> 1) * XP) << 2) + (((y + 1) & 1) << 1);
                const unsigned rb11 = ((3u * COPY_ENT + ((unsigned)(y + 1) >> 1) * XP) << 2) + (((y + 1) & 1) << 1);

                unsigned int u0 = __ldg(pu + rb00 + xp0);
                unsigned int u1 = __ldg(pu + rb01 + xp1);
                unsigned int u2 = __ldg(pu + rb10 + xp0);
                unsigned int u3 = __ldg(pu + rb11 + xp1);

                __half2 h = __hadd2(__hadd2(*reinterpret_cast<__half2*>(&u0),
                                            *reinterpret_cast<__half2*>(&u1)),
                                    __hadd2(*reinterpret_cast<__half2*>(&u2),
                                            *reinterpret_cast<__half2*>(&u3)));
                const float2 v = __half22float2(h);
                const float rt = __fdividef(v.y, v.x + 1e-9f);
                sum += rt * rt;
            }
        }
    } else {
        // Smoothness: REG_WEIGHT * sum( sqrt(d^2 + 1e-6) ) over flow dx & dy
        float ssum = 0.0f;
        const int total_flow = BB * 2 * HWPIX;
        const int nthreads = gridDim.x * gridDim.y * RBX;
        for (int i = (blockIdx.y * gridDim.x + blockIdx.x) * RBX + threadIdx.x;
             i < total_flow; i += nthreads) {
            const int o = i % HWPIX;
            const int h = o / WW;
            const int w = o % WW;
            const float v = flow[i];
            if (h < HH - 1) {
                const float d = v - flow[i + WW];
                ssum += sqrtf(d * d + 1e-6f);
            }
            if (w < WW - 1) {
                const float d = v - flow[i + 1];
                ssum += sqrtf(d * d + 1e-6f);
            }
        }
        sum = ssum * REG_WEIGHT;
    }

    block_reduce_add(sum);

    // Last finishing block writes the scalar.
    __threadfence();
    if (threadIdx.x == 0) {
        const unsigned int nblocks = gridDim.x * gridDim.y * gridDim.z;
        unsigned int old = atomicAdd(G_CTR_PTR, 1u);
        if (old == nblocks - 1) {
            out[0] = (float)(*G_LOSS_PTR);
        }
    }
}

extern "C" void kernel_launch(void* const* d_in, const int* in_sizes, int n_in,
                              void* d_out, int out_size) {
    const float* flow       = (const float*)d_in[0];  // 8*2*256*336
    const float* event_list = (const float*)d_in[1];  // 8*262144*4
    // d_in[2] = pol_mask (unused; polarity derived from event_list[...,3])
    float* out = (float*)d_out;

    void* acc_ptr = nullptr;
    cudaGetSymbolAddress(&acc_ptr, g_acc);

    // Single memset clears accumulators, loss scalar, and done-counter.
    cudaMemsetAsync(acc_ptr, 0, sizeof(unsigned long long) * (NULL_WORDS + 2), 0);

    scatter_kernel<<<dim3(NEV / 256, BB), 256>>>(flow, event_list);
    fused_reduce_kernel<<<dim3(2, 32, 33), RBX>>>(flow, out);
}

// round 11
// speedup vs baseline: 1.8429x; 1.8429x over previous
#include <cuda_runtime.h>
#include <cuda_fp16.h>
#include <cuda_bf16.h>
#include <math.h>

// Problem constants (match reference_code)
#define HH 256
#define WW 336
#define HWPIX (HH * WW)            // 86016
#define BB 8
#define NEV 262144
#define FLOW_SCALING 336.0f
#define REG_WEIGHT 0.001f

// ---------------------------------------------------------------------------
// Accumulator: 16B "quad" entries, 4 parity-shifted copies.
// Quad (16B) = 4 cells f16x2 {iwe, iwe_ts}:
//   lane0=(y0,x0) lane1=(y0,x0+1) lane2=(y0+1,x0) lane3=(y0+1,x0+1)
// Copy (cy,cx): quad(j,k) covers rows 2j-cy..2j-cy+1, cols 2k-cx..2k-cx+1.
// Bilinear block (ty..ty+1, lx..lx+1) -> ONE aligned quad in copy (ty&1, lx&1).
// ---------------------------------------------------------------------------
#define NPLANES 32                 // b(8) x tref(2) x p(2)
#define RP 130
#define XP 170
#define COPY_ENT ((size_t)RP * XP)            // 22100 quads
#define PLANE_ENT (4 * COPY_ENT)              // 88400 quads
#define NQUAD ((size_t)NPLANES * PLANE_ENT)   // ~45MB

#define NULL_WORDS (NQUAD * 2)
__device__ __align__(16) unsigned long long g_acc[NULL_WORDS + 2];

#define G_LOSS_PTR (reinterpret_cast<double*>(&g_acc[NULL_WORDS]))
#define G_CTR_PTR  (reinterpret_cast<unsigned int*>(&g_acc[NULL_WORDS + 1]))

__device__ __forceinline__ void red_quad(void* entry,
                                         __half2 a, __half2 b, __half2 c, __half2 d) {
    unsigned int ua = *reinterpret_cast<unsigned int*>(&a);
    unsigned int ub = *reinterpret_cast<unsigned int*>(&b);
    unsigned int uc = *reinterpret_cast<unsigned int*>(&c);
    unsigned int ud = *reinterpret_cast<unsigned int*>(&d);
    asm volatile("red.global.add.noftz.v4.f16x2 [%0], {%1, %2, %3, %4};"
                 :: "l"(entry), "r"(ua), "r"(ub), "r"(uc), "r"(ud) : "memory");
}

// ---------------------------------------------------------------------------
// Scatter: grid (NEV/256, B). One thread per event, 2 REDs per event.
// ---------------------------------------------------------------------------
__global__ void __launch_bounds__(256) scatter_kernel(
    const float* __restrict__ flow,       // [B,2,H,W]
    const float* __restrict__ event_list) // [B,N,4] = {t, y, x, pol(+-1)}
{
    const int i = blockIdx.x * 256 + threadIdx.x;   // event index within batch
    const int b = blockIdx.y;

    const float4 e = reinterpret_cast<const float4*>(event_list)[(size_t)b * NEV + i];
    const float ts = e.x;
    const float yy = e.y;
    const float xx = e.z;
    const int   p  = (e.w > 0.0f) ? 0 : 1;   // pol_mask: col0=(pol==1), col1=(pol==0)

    const int pix = (int)yy * WW + (int)xx;
    const float* fb = flow + (size_t)b * 2 * HWPIX;
    const float dxf = fb[pix] * FLOW_SCALING;           // x-flow * scale
    const float dyf = fb[HWPIX + pix] * FLOW_SCALING;   // y-flow * scale

    // tref=0: w = pos - ts*flow ; tref=1: w = pos + (1-ts)*flow = w0 + flow
    const float wy_t[2] = { fmaf(-ts, dyf, yy), fmaf(-ts, dyf, yy) + dyf };
    const float wx_t[2] = { fmaf(-ts, dxf, xx), fmaf(-ts, dxf, xx) + dxf };

#pragma unroll
    for (int tref = 0; tref < 2; ++tref) {
        const float wy = wy_t[tref];
        const float wx = wx_t[tref];
        const float tg = tref ? ts : (1.0f - ts);

        const float tyf = floorf(wy);
        const float lxf = floorf(wx);
        const int ty = (int)tyf;
        const int lx = (int)lxf;
        const float fry = wy - tyf;
        const float frx = wx - lxf;

        const float wy0 = ((unsigned)ty       < HH) ? (1.0f - fry) : 0.0f;
        const float wy1 = ((unsigned)(ty + 1) < HH) ? fry          : 0.0f;
        const float wxl = ((unsigned)lx       < WW) ? (1.0f - frx) : 0.0f;
        const float wxr = ((unsigned)(lx + 1) < WW) ? frx          : 0.0f;

        if ((wy0 + wy1) * (wxl + wxr) == 0.0f) continue;

        const int tyc = min(max(ty, -1), HH - 1);
        const int lxc = min(max(lx, -1), WW - 1);

        const int cy = tyc & 1;
        const int cx = lxc & 1;
        const int j  = (tyc + cy) >> 1;
        const int k  = (lxc + cx) >> 1;
        const int plane = ((b * 2 + tref) * 2 + p);

        const size_t entry = (size_t)plane * PLANE_ENT
                           + (size_t)(cy * 2 + cx) * COPY_ENT
                           + (size_t)j * XP + k;

        const float w00 = wy0 * wxl, w01 = wy0 * wxr;
        const float w10 = wy1 * wxl, w11 = wy1 * wxr;

        red_quad(reinterpret_cast<char*>(g_acc) + entry * 16,
                 __floats2half2_rn(w00, w00 * tg),
                 __floats2half2_rn(w01, w01 * tg),
                 __floats2half2_rn(w10, w10 * tg),
                 __floats2half2_rn(w11, w11 * tg));
    }
}

// ---------------------------------------------------------------------------
// Block reduction helper (f32 partials -> double atomic)
// ---------------------------------------------------------------------------
__device__ __forceinline__ void block_reduce_add(float v) {
    __shared__ float sdata[32];
    const int lane = threadIdx.x & 31;
    const int warp = threadIdx.x >> 5;
#pragma unroll
    for (int off = 16; off > 0; off >>= 1)
        v += __shfl_down_sync(0xffffffffu, v, off);
    if (lane == 0) sdata[warp] = v;
    __syncthreads();
    if (warp == 0) {
        const int nwarps = (blockDim.x + 31) >> 5;
        float s = (lane < nwarps) ? sdata[lane] : 0.0f;
#pragma unroll
        for (int off = 16; off > 0; off >>= 1)
            s += __shfl_down_sync(0xffffffffu, s, off);
        if (lane == 0) atomicAdd(G_LOSS_PTR, (double)s);
    }
}

// ---------------------------------------------------------------------------
// Fused reduce, 3D grid: (2, 32, 33).
//   Phase A (blocks z<32): per-plane cell loss, block-uniform row addressing.
//   Phase B (ALL blocks): smoothness, grid-stride over the FULL 405K threads
//     (the R10 regression was giving this phase only 64 blocks -> 112 serial
//      latency-bound iterations per thread; now ~3.4 each).
// Last finishing block writes the output scalar.
// ---------------------------------------------------------------------------
#define RBX 192          // threads per block (168 active on cell work)
#define RXW 168          // cells per block in x

__global__ void __launch_bounds__(RBX) fused_reduce_kernel(
    const float* __restrict__ flow, float* __restrict__ out)
{
    float sum = 0.0f;

    // ---- Phase A: accumulator loss (blocks with z < NPLANES) ----
    if (blockIdx.z < NPLANES) {
        const int plane = blockIdx.z;
        const int x = blockIdx.x * RXW + threadIdx.x;

        if (threadIdx.x < RXW) {
            const unsigned int* pu = reinterpret_cast<const unsigned int*>(g_acc)
                                   + (size_t)plane * PLANE_ENT * 4;
            // x-dependent (lane) address parts for cx=0 / cx=1
            const unsigned xp0 = ((unsigned)(x)     >> 1 << 2) + (x & 1);
            const unsigned xp1 = ((unsigned)(x + 1) >> 1 << 2) + ((x + 1) & 1);

#pragma unroll
            for (int r = 0; r < 8; ++r) {
                const int y = blockIdx.y * 8 + r;
                // block-uniform row bases per copy (cy,cx)
                const unsigned rb00 = ((0u * COPY_ENT + ((unsigned)y       >> 1) * XP) << 2) + (((y)     & 1) << 1);
                const unsigned rb01 = ((1u * COPY_ENT + ((unsigned)y       >> 1) * XP) << 2) + (((y)     & 1) << 1);
                const unsigned rb10 = ((2u * COPY_ENT + ((unsigned)(y + 1) >> 1) * XP) << 2) + (((y + 1) & 1) << 1);
                const unsigned rb11 = ((3u * COPY_ENT + ((unsigned)(y + 1) >> 1) * XP) << 2) + (((y + 1) & 1) << 1);

                unsigned int u0 = __ldg(pu + rb00 + xp0);
                unsigned int u1 = __ldg(pu + rb01 + xp1);
                unsigned int u2 = __ldg(pu + rb10 + xp0);
                unsigned int u3 = __ldg(pu + rb11 + xp1);

                __half2 h = __hadd2(__hadd2(*reinterpret_cast<__half2*>(&u0),
                                            *reinterpret_cast<__half2*>(&u1)),
                                    __hadd2(*reinterpret_cast<__half2*>(&u2),
                                            *reinterpret_cast<__half2*>(&u3)));
                const float2 v = __half22float2(h);
                const float rt = __fdividef(v.y, v.x + 1e-9f);
                sum += rt * rt;
            }
        }
    }

    // ---- Phase B: smoothness, ALL blocks participate ----
    {
        const int flat_bid = (blockIdx.z * gridDim.y + blockIdx.y) * gridDim.x
                           + blockIdx.x;
        const int nthreads = gridDim.x * gridDim.y * gridDim.z * RBX;
        float ssum = 0.0f;
        const int total_flow = BB * 2 * HWPIX;
        for (int i = flat_bid * RBX + threadIdx.x; i < total_flow; i += nthreads) {
            const int o = i % HWPIX;
            const int h = o / WW;
            const int w = o % WW;
            const float v = flow[i];
            if (h < HH - 1) {
                const float d = v - flow[i + WW];
                ssum += sqrtf(d * d + 1e-6f);
            }
            if (w < WW - 1) {
                const float d = v - flow[i + 1];
                ssum += sqrtf(d * d + 1e-6f);
            }
        }
        sum += ssum * REG_WEIGHT;
    }

    block_reduce_add(sum);

    // Last finishing block writes the scalar.
    __threadfence();
    if (threadIdx.x == 0) {
        const unsigned int nblocks = gridDim.x * gridDim.y * gridDim.z;
        unsigned int old = atomicAdd(G_CTR_PTR, 1u);
        if (old == nblocks - 1) {
            out[0] = (float)(*G_LOSS_PTR);
        }
    }
}

extern "C" void kernel_launch(void* const* d_in, const int* in_sizes, int n_in,
                              void* d_out, int out_size) {
    const float* flow       = (const float*)d_in[0];  // 8*2*256*336
    const float* event_list = (const float*)d_in[1];  // 8*262144*4
    // d_in[2] = pol_mask (unused; polarity derived from event_list[...,3])
    float* out = (float*)d_out;

    void* acc_ptr = nullptr;
    cudaGetSymbolAddress(&acc_ptr, g_acc);

    // Single memset clears accumulators, loss scalar, and done-counter.
    cudaMemsetAsync(acc_ptr, 0, sizeof(unsigned long long) * (NULL_WORDS + 2), 0);

    scatter_kernel<<<dim3(NEV / 256, BB), 256>>>(flow, event_list);
    fused_reduce_kernel<<<dim3(2, 32, 33), RBX>>>(flow, out);
}